// round 8
// baseline (speedup 1.0000x reference)
#include <cuda_runtime.h>

#define NQ 12
#define NT 256
#define NL 2

typedef unsigned long long u64;

// ---- packed f32x2 helpers ----
__device__ __forceinline__ u64 pack2(float lo, float hi) {
    u64 v; asm("mov.b64 %0, {%1, %2};" : "=l"(v) : "f"(lo), "f"(hi)); return v;
}
__device__ __forceinline__ void unpack2(u64 v, float &lo, float &hi) {
    asm("mov.b64 {%0, %1}, %2;" : "=f"(lo), "=f"(hi) : "l"(v));
}
__device__ __forceinline__ u64 swap2(u64 v) {
    float lo, hi; unpack2(v, lo, hi); return pack2(hi, lo);
}
__device__ __forceinline__ u64 fma2(u64 a, u64 b, u64 c) {
    u64 d; asm("fma.rn.f32x2 %0, %1, %2, %3;" : "=l"(d) : "l"(a), "l"(b), "l"(c)); return d;
}
__device__ __forceinline__ u64 mul2(u64 a, u64 b) {
    u64 d; asm("mul.rn.f32x2 %0, %1, %2;" : "=l"(d) : "l"(a), "l"(b)); return d;
}
__device__ __forceinline__ u64 add2(u64 a, u64 b) {
    u64 d; asm("add.rn.f32x2 %0, %1, %2;" : "=l"(d) : "l"(a), "l"(b)); return d;
}

// State: X[j] = (re[j], re[j|8]), Y[j] = (im[j], im[j|8]), j = slot bits 0-2,
// packed half = slot bit 3. Slot s = wp*512 + lane*16 + r.
// Reference convention: qubit j <-> logical bit (11-j).

template<int B>
__device__ __forceinline__ void rx_low(u64 (&X)[8], u64 (&Y)[8],
                                       u64 c2, u64 s2, u64 sn2) {
    #pragma unroll
    for (int j = 0; j < 8; j++) {
        if (!((j >> B) & 1)) {
            const int j1 = j | (1 << B);
            u64 x0 = X[j], x1 = X[j1], y0 = Y[j], y1 = Y[j1];
            X[j]  = fma2(c2, x0, mul2(s2,  y1));
            X[j1] = fma2(c2, x1, mul2(s2,  y0));
            Y[j]  = fma2(c2, y0, mul2(sn2, x1));
            Y[j1] = fma2(c2, y1, mul2(sn2, x0));
        }
    }
}

__device__ __forceinline__ void rx_b3(u64 (&X)[8], u64 (&Y)[8],
                                      u64 c2, u64 s2, u64 sn2) {
    #pragma unroll
    for (int j = 0; j < 8; j++) {
        u64 sx = swap2(X[j]);
        u64 sy = swap2(Y[j]);
        X[j] = fma2(c2, X[j], mul2(s2,  sy));
        Y[j] = fma2(c2, Y[j], mul2(sn2, sx));
    }
}

// 4 RX gates of one frame: reg bits 0,1,2 then the packed bit.
__device__ __forceinline__ void frame_gates(u64 (&X)[8], u64 (&Y)[8],
                                            const float4* t4) {
    #pragma unroll
    for (int q = 0; q < 4; q++) {
        float4 t = t4[q];                  // (c, c, s, s) -> one LDS.128
        u64 c2 = pack2(t.x, t.y);
        u64 s2 = pack2(t.z, t.w);
        u64 sn2 = s2 ^ 0x8000000080000000ULL;
        if (q == 0) rx_low<0>(X, Y, c2, s2, sn2);
        else if (q == 1) rx_low<1>(X, Y, c2, s2, sn2);
        else if (q == 2) rx_low<2>(X, Y, c2, s2, sn2);
        else rx_b3(X, Y, c2, s2, sn2);
    }
}

__global__ void __launch_bounds__(NT, 4)
qsim_kernel(const float* __restrict__ x, const float* __restrict__ w,
            float* __restrict__ out) {
    __shared__ float2 sbuf[4096];
    __shared__ float4 trig[NL + 1][NQ];     // (c, c, s, s), indexed by logical BIT
    __shared__ float w_acc[NT / 32][NQ];

    const int tid  = threadIdx.x;
    const int lane = tid & 31;
    const int wp   = tid >> 5;
    const int blk  = blockIdx.x;

    if (tid < NQ * (NL + 1)) {
        int l = tid / NQ, q = tid % NQ;
        float th = 0.5f * (l == 0 ? x[blk * NQ + (NQ - 1 - q)]
                                  : w[(l - 1) * NQ + (NQ - 1 - q)]);
        float c = cosf(th), s = sinf(th);
        trig[l][q] = make_float4(c, c, s, s);
    }
    __syncthreads();

    u64 X[8], Y[8];

    // ---- init: product state after input RX layer on |0...0> ----
    {
        float mh = 1.0f;
        #pragma unroll
        for (int b = 0; b < 8; b++) {
            float4 t = trig[0][b + 4];
            mh *= ((tid >> b) & 1) ? t.z : t.x;
        }
        const int pch = __popc(tid);
        const float4 t3 = trig[0][3];
        #pragma unroll
        for (int j = 0; j < 8; j++) {
            float mj = mh;
            #pragma unroll
            for (int b = 0; b < 3; b++) {
                float4 t = trig[0][b];
                mj *= ((j >> b) & 1) ? t.z : t.x;
            }
            float mlo = mj * t3.x, mhi = mj * t3.z;
            int pc  = (pch + __popc(j)) & 3;
            int pc2 = (pc + 1) & 3;
            float relo = (pc  == 0) ?  mlo : (pc  == 2) ? -mlo : 0.0f;
            float imlo = (pc  == 1) ? -mlo : (pc  == 3) ?  mlo : 0.0f;
            float rehi = (pc2 == 0) ?  mhi : (pc2 == 2) ? -mhi : 0.0f;
            float imhi = (pc2 == 1) ? -mhi : (pc2 == 3) ?  mhi : 0.0f;
            X[j] = pack2(relo, rehi);
            Y[j] = pack2(imlo, imhi);
        }
    }

    #pragma unroll 1
    for (int l = 1; l <= NL; l++) {
        // ---- frame I: reg bits = logical 0-3 ----
        frame_gates(X, Y, &trig[l][0]);

        // ---- T1: swap slot bits 0-3 <-> 4-7 (warp-local: stripe bits 5-7 = wp) ----
        if (l == 2) __syncthreads();       // other warps' T3 gathers read our stripe
        #pragma unroll
        for (int j = 0; j < 8; j++) {
            int a = (j << 8) | (wp << 5) | (lane ^ j);
            float xl, xh, yl, yh;
            unpack2(X[j], xl, xh);
            unpack2(Y[j], yl, yh);
            sbuf[a]         = make_float2(xl, yl);
            sbuf[a ^ 0x808] = make_float2(xh, yh);
        }
        __syncwarp();
        {
            const int g1 = ((lane & 15) << 8) | (wp << 5) | (lane & 16);
            #pragma unroll
            for (int j = 0; j < 8; j++) {
                int a = g1 | (j ^ (lane & 15));
                float2 t0 = sbuf[a];
                float2 t1 = sbuf[a ^ 8];
                X[j] = pack2(t0.x, t1.x);
                Y[j] = pack2(t0.y, t1.y);
            }
        }

        // ---- frame f1: reg bits = logical 4-7 ----
        frame_gates(X, Y, &trig[l][4]);

        // ---- T2: swap slot bits 0-3 <-> 8-11 (store own stripe, gather crosses) ----
        __syncwarp();                      // own warp's T1 gather must precede overwrite
        #pragma unroll
        for (int j = 0; j < 8; j++) {
            int a = (j << 8) | (wp << 5) | (lane ^ ((j & 1) << 4));
            float xl, xh, yl, yh;
            unpack2(X[j], xl, xh);
            unpack2(Y[j], yl, yh);
            sbuf[a]         = make_float2(xl, yl);
            sbuf[a ^ 0x800] = make_float2(xh, yh);
        }
        __syncthreads();
        {
            const int g2 = (((lane >> 4) | (wp << 1)) << 8) | (lane & 15)
                         | (((lane >> 4) & 1) << 4);
            #pragma unroll
            for (int j = 0; j < 8; j++) {
                int a = (g2 ^ ((j & 1) << 4)) | ((j >> 1) << 5);
                float2 t0 = sbuf[a];
                float2 t1 = sbuf[a ^ 0x80];
                X[j] = pack2(t0.x, t1.x);
                Y[j] = pack2(t0.y, t1.y);
            }
        }

        // ---- frame f2: reg bits = logical 8-11 ----
        frame_gates(X, Y, &trig[l][8]);

        if (l == 1) {
            // ---- T3: back to frame I with all 12 CNOTs folded ----
            __syncthreads();               // all T2 gathers done before overwrite
            #pragma unroll
            for (int j = 0; j < 8; j++) {
                int a = (j << 8) | (wp << 5) | (lane ^ wp);
                float xl, xh, yl, yh;
                unpack2(X[j], xl, xh);
                unpack2(Y[j], yl, yh);
                sbuf[a]         = make_float2(xl, yl);
                sbuf[a ^ 0x800] = make_float2(xh, yh);
            }
            __syncthreads();
            #pragma unroll
            for (int j = 0; j < 8; j++) {
                int s  = (wp << 9) | (lane << 4) | j;
                int P  = ((s ^ (s >> 1)) & 0x3FF)
                       | ((((s >> 10) ^ (s >> 11) ^ s) & 1) << 10)
                       | ((((s >> 11) ^ s) & 1) << 11);
                int ru = P >> 8;
                int wu = (P >> 5) & 7;
                int lu = P & 31;
                int a0 = (ru << 8) | (wu << 5) | (lu ^ wu);
                float2 t0 = sbuf[a0];
                float2 t1 = sbuf[a0 ^ 0xC];   // slot bit 3 flip => P bits 2,3 flip
                X[j] = pack2(t0.x, t1.x);
                Y[j] = pack2(t0.y, t1.y);
            }
        }
        // l == 2: stay in frame f2 with pending ring perm; folded below.
    }

    // ---- expectations (frame f2 + pending perm folded into signs) ----
    const u64 one2  = pack2(1.0f, 1.0f);
    const u64 mone2 = pack2(-1.0f, -1.0f);
    u64 Dp, Ep, Fp;
    {
        u64 P = fma2(X[0], X[0], mul2(Y[0], Y[0]));
        Dp = P; Ep = P; Fp = P;
    }
    #pragma unroll
    for (int j = 1; j < 8; j++) {
        u64 P = fma2(X[j], X[j], mul2(Y[j], Y[j]));
        Dp = fma2((__popc(j) & 1) ? mone2 : one2, P, Dp);
        Ep = fma2((((j >> 1) ^ (j >> 2)) & 1) ? mone2 : one2, P, Ep);
        Fp = fma2(((j >> 2) & 1) ? mone2 : one2, P, Fp);
    }
    u64 DG, EF;
    {
        float dlo, dhi, elo, ehi, flo, fhi;
        unpack2(Dp, dlo, dhi);
        unpack2(Ep, elo, ehi);
        unpack2(Fp, flo, fhi);
        DG = pack2(dlo - dhi, dlo + dhi);
        EF = pack2(elo - ehi, flo - fhi);
    }

    // Packed Walsh-Hadamard over the 5 lane bits on (D,G); allreduce on (E,F).
    #pragma unroll
    for (int st = 0; st < 5; st++) {
        const int m = 1 << st;
        u64 tD = __shfl_xor_sync(0xffffffffu, DG, m);
        u64 tE = __shfl_xor_sync(0xffffffffu, EF, m);
        DG = fma2((lane & m) ? mone2 : one2, DG, tD);
        EF = add2(EF, tE);
    }

    {
        float cD, cG, cE, cF;
        unpack2(DG, cD, cG);
        unpack2(EF, cE, cF);
        const int pw = __popc(wp) & 1;
        const float sD = pw ? -cD : cD;
        if (lane == 31) {
            w_acc[wp][0]  = sD;
            w_acc[wp][11] = pw ? -cG : cG;
        } else if (lane == 30) w_acc[wp][1] = sD;
        else if (lane == 28)   w_acc[wp][2] = sD;
        else if (lane == 24)   w_acc[wp][3] = sD;
        else if (lane == 16)   w_acc[wp][4] = sD;
        else if (lane == 0) {
            w_acc[wp][5] = sD;
            w_acc[wp][6] = (((wp >> 1) ^ (wp >> 2)) & 1) ? -cD : cD;
            w_acc[wp][7] = ((wp >> 2) & 1) ? -cD : cD;
            w_acc[wp][8] = cD;
            w_acc[wp][9] = cE;
            w_acc[wp][10] = cF;
        }
    }
    __syncthreads();
    if (tid < NQ) {
        float v = 0.0f;
        #pragma unroll
        for (int wi = 0; wi < NT / 32; wi++) v += w_acc[wi][tid];
        out[blk * NQ + (NQ - 1 - tid)] = v;
    }
}

extern "C" void kernel_launch(void* const* d_in, const int* in_sizes, int n_in,
                              void* d_out, int out_size) {
    const float* x = (const float*)d_in[0];   // (B, 12) float32
    const float* w = (const float*)d_in[1];   // (2, 12) float32
    float* out = (float*)d_out;               // (B, 12) float32
    int B = in_sizes[0] / NQ;
    qsim_kernel<<<B, NT>>>(x, w, out);
}